// round 6
// baseline (speedup 1.0000x reference)
#include <cuda_runtime.h>
#include <math.h>

#define Bn   512
#define Nn   199
#define NP   200          // padded nodes
#define Fn   64
#define Hn   4
#define Un   64
#define OUTC 455          // H*U + N
#define KROW 224          // padded kernels row (j = l + 32k, k<7)
#define NT   512
#define NW   16
#define NCHUNK 32         // 4 chunks of 8 rows + 28 chunks of 6 rows
#define RSP  8            // padded wb row stride (floats)

typedef unsigned long long u64;

// chunk-blocked weighted adjacency: g_Gc[h][c][n][q] = A[n,m]*P[h,n,m],
// m = m0(c)+q (zero beyond chunk rows / graph), rows 32B-aligned.
__device__ float g_Gc[Hn * NCHUNK * NP * RSP];

__device__ __forceinline__ u64 fma2(u64 a, u64 b, u64 c) {
    u64 d; asm("fma.rn.f32x2 %0, %1, %2, %3;" : "=l"(d) : "l"(a), "l"(b), "l"(c));
    return d;
}
__device__ __forceinline__ u64 pack2(float lo, float hi) {
    u64 d; asm("mov.b64 %0, {%1, %2};" : "=l"(d) : "f"(lo), "f"(hi)); return d;
}
__device__ __forceinline__ float2 unpack2(u64 v) {
    float2 r; asm("mov.b64 {%0, %1}, %2;" : "=f"(r.x), "=f"(r.y) : "l"(v)); return r;
}

// wide pair-block load/store: pairs p=0..PAIRS-1 at 8-byte slots of a 32B row
template<int PAIRS>
__device__ __forceinline__ void ld_pairs(const float* src, u64* v) {
    ulonglong2 a = *(const ulonglong2*)src;
    v[0] = a.x; v[1] = a.y;
    if (PAIRS == 4) { ulonglong2 c = *(const ulonglong2*)(src + 4); v[2] = c.x; v[3] = c.y; }
    else            { v[2] = *(const u64*)(src + 4); }
}
template<int PAIRS>
__device__ __forceinline__ void st_pairs(float* dst, const u64* v) {
    *(ulonglong2*)dst = make_ulonglong2(v[0], v[1]);
    if (PAIRS == 4) *(ulonglong2*)(dst + 4) = make_ulonglong2(v[2], v[3]);
    else            *(u64*)(dst + 4) = v[2];
}

__global__ void prep_g(const float* __restrict__ A, const float* __restrict__ P) {
    int i = blockIdx.x * blockDim.x + threadIdx.x;
    if (i >= Hn * NCHUNK * NP * RSP) return;
    int q = i & (RSP - 1);
    int n = (i / RSP) % NP;
    int c = (i / (RSP * NP)) % NCHUNK;
    int h = i / (RSP * NP * NCHUNK);
    int rows = (c < 4) ? 8 : 6;
    int m0   = (c < 4) ? 8 * c : 32 + 6 * (c - 4);
    int m = m0 + q;
    float v = 0.f;
    if (q < rows && n < Nn && m < Nn)
        v = A[n * Nn + m] * P[(h * Nn + n) * Nn + m];
    g_Gc[i] = v;
}

// One chunk of 2*PAIRS m-rows, fully per-warp. wb: [NP][RSP] staging.
template<int PAIRS>
__device__ __forceinline__ void do_chunk(
    int c, int m0, int b, int h, int l, bool last_h,
    const float* __restrict__ Xs, const float* __restrict__ Ks,
    const float* __restrict__ fcs, const float* __restrict__ b1s,
    const float* __restrict__ b2s, float* __restrict__ wb,
    const float* __restrict__ A, float* __restrict__ out)
{
    // ---- feat[r][f] = sum_n G[n][r] * X[n][f]  (row-pair packed over f=2l,2l+1)
    u64 aX[PAIRS], aY[PAIRS];
    #pragma unroll
    for (int p = 0; p < PAIRS; p++) { aX[p] = 0ull; aY[p] = 0ull; }
    const float* Gc = g_Gc + (size_t)(h * NCHUNK + c) * (NP * RSP);
    #pragma unroll 4
    for (int n = 0; n < NP; n++) {
        float2 x = *(const float2*)&Xs[n * Fn + 2 * l];
        u64 xx = pack2(x.x, x.x), xy = pack2(x.y, x.y);
        u64 g[PAIRS];
        ld_pairs<PAIRS>(Gc + n * RSP, g);
        #pragma unroll
        for (int p = 0; p < PAIRS; p++) {
            aX[p] = fma2(g[p], xx, aX[p]);
            aY[p] = fma2(g[p], xy, aY[p]);
        }
    }
    __syncwarp();      // prior chunk's wb reads done before restaging
    st_pairs<PAIRS>(&wb[(2 * l) * RSP], aX);
    st_pairs<PAIRS>(&wb[(2 * l + 1) * RSP], aY);
    __syncwarp();

    // ---- dense[r][j] = sum_f feat[r][f]*K[f][j] + b1[j], j = l+32k
    u64 dP[PAIRS][7];
    #pragma unroll
    for (int k = 0; k < 7; k++) {
        float bv = b1s[l + 32 * k];
        u64 bb = pack2(bv, bv);
        #pragma unroll
        for (int p = 0; p < PAIRS; p++) dP[p][k] = bb;
    }
    #pragma unroll 2
    for (int f = 0; f < Fn; f++) {
        u64 fp[PAIRS];
        ld_pairs<PAIRS>(&wb[f * RSP], fp);
        #pragma unroll
        for (int k = 0; k < 7; k++) {
            float kv = Ks[f * KROW + l + 32 * k];
            u64 kk = pack2(kv, kv);
            #pragma unroll
            for (int p = 0; p < PAIRS; p++) dP[p][k] = fma2(fp[p], kk, dP[p][k]);
        }
    }
    __syncwarp();      // all wb(feat) reads done before mask overwrites

    // ---- adjacency-masked softmax per row
    #pragma unroll
    for (int p = 0; p < PAIRS; p++) {
        float2 dk[7];
        #pragma unroll
        for (int k = 0; k < 7; k++) dk[k] = unpack2(dP[p][k]);
        #pragma unroll
        for (int s = 0; s < 2; s++) {
            int r = 2 * p + s, m = m0 + r;
            if (m < Nn) {
                float dv[7], av[7];
                #pragma unroll
                for (int k = 0; k < 7; k++) dv[k] = s ? dk[k].y : dk[k].x;
                #pragma unroll
                for (int k = 0; k < 7; k++) {
                    int j = l + 32 * k;
                    av[k] = (j < Nn) ? A[m * Nn + j] : 0.f;
                }
                float mx = -3.0e38f;
                #pragma unroll
                for (int k = 0; k < 7; k++) if (av[k] != 0.f) mx = fmaxf(mx, dv[k]);
                #pragma unroll
                for (int o = 16; o > 0; o >>= 1)
                    mx = fmaxf(mx, __shfl_xor_sync(0xffffffffu, mx, o));
                float ssum = 0.f;
                #pragma unroll
                for (int k = 0; k < 7; k++) {
                    float e = (av[k] != 0.f) ? __expf(dv[k] - mx) : 0.f;
                    av[k] = e; ssum += e;
                }
                #pragma unroll
                for (int o = 16; o > 0; o >>= 1)
                    ssum += __shfl_xor_sync(0xffffffffu, ssum, o);
                float inv = 1.f / ssum;
                size_t mrow = ((size_t)b * Nn + m) * OUTC + Hn * Un;
                #pragma unroll
                for (int k = 0; k < 7; k++) {
                    int j = l + 32 * k;
                    float pv = av[k] * inv;
                    if (j < NP) wb[j * RSP + r] = pv;
                    if (last_h && j < Nn) out[mrow + j] = pv;
                }
            } else {
                #pragma unroll
                for (int k = 0; k < 7; k++) {
                    int j = l + 32 * k;
                    if (j < NP) wb[j * RSP + r] = 0.f;
                }
            }
        }
    }
    __syncwarp();

    // ---- node[r][f] = sum_j mask[r][j] * X[j][f]  (row-pair packed)
    u64 nX[PAIRS], nY[PAIRS];
    #pragma unroll
    for (int p = 0; p < PAIRS; p++) { nX[p] = 0ull; nY[p] = 0ull; }
    #pragma unroll 4
    for (int j = 0; j < NP; j++) {
        float2 x = *(const float2*)&Xs[j * Fn + 2 * l];
        u64 xx = pack2(x.x, x.x), xy = pack2(x.y, x.y);
        u64 mm[PAIRS];
        ld_pairs<PAIRS>(&wb[j * RSP], mm);
        #pragma unroll
        for (int p = 0; p < PAIRS; p++) {
            nX[p] = fma2(mm[p], xx, nX[p]);
            nY[p] = fma2(mm[p], xy, nY[p]);
        }
    }
    __syncwarp();      // mask reads done before node staging overwrites
    st_pairs<PAIRS>(&wb[(2 * l) * RSP], nX);
    st_pairs<PAIRS>(&wb[(2 * l + 1) * RSP], nY);
    __syncwarp();

    // ---- out[r][u] = sum_f node[r][f] * fc[f][u] + b2[u]
    u64 oX[PAIRS], oY[PAIRS];
    {
        u64 bx = pack2(b2s[2 * l], b2s[2 * l]);
        u64 by = pack2(b2s[2 * l + 1], b2s[2 * l + 1]);
        #pragma unroll
        for (int p = 0; p < PAIRS; p++) { oX[p] = bx; oY[p] = by; }
    }
    #pragma unroll 2
    for (int f = 0; f < Fn; f++) {
        float2 cc = *(const float2*)&fcs[f * Un + 2 * l];
        u64 cx = pack2(cc.x, cc.x), cy = pack2(cc.y, cc.y);
        u64 nn[PAIRS];
        ld_pairs<PAIRS>(&wb[f * RSP], nn);
        #pragma unroll
        for (int p = 0; p < PAIRS; p++) {
            oX[p] = fma2(nn[p], cx, oX[p]);
            oY[p] = fma2(nn[p], cy, oY[p]);
        }
    }
    #pragma unroll
    for (int p = 0; p < PAIRS; p++) {
        float2 vx = unpack2(oX[p]);   // rows (2p, 2p+1) at u = 2l
        float2 vy = unpack2(oY[p]);   // rows (2p, 2p+1) at u = 2l+1
        int m = m0 + 2 * p;
        if (m < Nn) {
            float* o = out + ((size_t)b * Nn + m) * OUTC + h * Un;
            o[2 * l] = vx.x; o[2 * l + 1] = vy.x;
        }
        if (m + 1 < Nn) {
            float* o = out + ((size_t)b * Nn + m + 1) * OUTC + h * Un;
            o[2 * l] = vx.y; o[2 * l + 1] = vy.y;
        }
    }
    __syncwarp();
}

// smem: Xs 51200 | Ks 57344 | fcs 16384 | wbuf 102400 | b1s 896 | b2s 256 = 228,480 B
#define WBUF_FLOATS (NW * NP * RSP)

__global__ __launch_bounds__(NT, 1)
void gc_kernel(const float* __restrict__ X, const float* __restrict__ A,
               const float* __restrict__ KER, const float* __restrict__ FC,
               const float* __restrict__ B1, const float* __restrict__ B2,
               float* __restrict__ out)
{
    extern __shared__ float sm[];
    float* Xs   = sm;                      // [NP][Fn]
    float* Ks   = Xs + NP * Fn;            // [Fn][KROW]
    float* fcs  = Ks + Fn * KROW;          // [Fn][Un]
    float* wbuf = fcs + Fn * Un;           // [NW][NP][RSP]
    float* b1s  = wbuf + WBUF_FLOATS;      // [KROW]
    float* b2s  = b1s + KROW;              // [Un]

    const int b = blockIdx.x / Hn;
    const int h = blockIdx.x - b * Hn;
    const int tid = threadIdx.x;
    const int w = tid >> 5;
    const int l = tid & 31;
    const bool last_h = (h == Hn - 1);

    // ---------------- load phase ----------------
    {
        const float4* xg = (const float4*)(X + (size_t)b * (Nn * Fn));
        float4* xs4 = (float4*)Xs;
        for (int i = tid; i < NP * Fn / 4; i += NT)
            xs4[i] = (i < Nn * Fn / 4) ? xg[i] : make_float4(0.f, 0.f, 0.f, 0.f);

        const float* kg = KER + (size_t)h * (Fn * Nn);
        for (int i = tid; i < Fn * KROW; i += NT) {
            int f = i / KROW, j = i - f * KROW;
            Ks[i] = (j < Nn) ? kg[f * Nn + j] : 0.f;
        }
        const float4* fg = (const float4*)(FC + (size_t)h * (Fn * Un));
        float4* fcs4 = (float4*)fcs;
        for (int i = tid; i < Fn * Un / 4; i += NT) fcs4[i] = fg[i];

        for (int i = tid; i < KROW; i += NT) b1s[i] = (i < Nn) ? B1[h * Nn + i] : 0.f;
        if (tid < Un) b2s[tid] = B2[h * Un + tid];
    }
    __syncthreads();

    float* wb = wbuf + w * (NP * RSP);

    // schedule: 200 rows = 4x(8-row chunk) + 28x(6-row chunk); 12% max imbalance
    if (w < 4) {
        do_chunk<4>(w,     8 * w,      b, h, l, last_h, Xs, Ks, fcs, b1s, b2s, wb, A, out);
        do_chunk<3>(4 + w, 32 + 6 * w, b, h, l, last_h, Xs, Ks, fcs, b1s, b2s, wb, A, out);
    } else {
        int t0 = 4 + 2 * (w - 4);
        do_chunk<3>(4 + t0,     32 + 6 * t0,       b, h, l, last_h, Xs, Ks, fcs, b1s, b2s, wb, A, out);
        do_chunk<3>(4 + t0 + 1, 32 + 6 * (t0 + 1), b, h, l, last_h, Xs, Ks, fcs, b1s, b2s, wb, A, out);
    }
}

static const size_t SMEM_BYTES =
    (size_t)(NP * Fn + Fn * KROW + Fn * Un + WBUF_FLOATS + KROW + Un) * 4;

extern "C" void kernel_launch(void* const* d_in, const int* in_sizes, int n_in,
                              void* d_out, int out_size) {
    const float* X   = (const float*)d_in[0];
    const float* A   = (const float*)d_in[1];
    const float* KER = (const float*)d_in[2];
    const float* P   = (const float*)d_in[3];
    const float* FC  = (const float*)d_in[4];
    const float* B1  = (const float*)d_in[5];
    const float* B2  = (const float*)d_in[6];
    float* out = (float*)d_out;

    cudaFuncSetAttribute(gc_kernel, cudaFuncAttributeMaxDynamicSharedMemorySize,
                         (int)SMEM_BYTES);

    prep_g<<<(Hn * NCHUNK * NP * RSP + 255) / 256, 256>>>(A, P);
    gc_kernel<<<Bn * Hn, NT, SMEM_BYTES>>>(X, A, KER, FC, B1, B2, out);
}

// round 7
// speedup vs baseline: 1.4770x; 1.4770x over previous
#include <cuda_runtime.h>
#include <math.h>
#include <stdint.h>

#define Bn   512
#define Nn   199
#define Hn   4
#define Fn   64
#define Un   64
#define OUTC 455           // H*U + N
#define MT   13            // m16 tiles covering 200 rows (208)
#define KT   25            // k/j tiles of 8 covering 200
#define FT   8             // f/u tiles of 8 (64)
#define THREADS 512
#define XST  210           // XsT row stride (conflict-free for frag loads)

// Preprocessed operand banks (global, L2-resident)
__device__ float g_Ga[Hn * MT * KT * 32 * 4];  // feat A-frags: G[m][n] tf32
__device__ float g_Kb[Hn * KT * FT * 32 * 2];  // dense B-frags: K[f][j] tf32
__device__ float g_Fb[Hn * FT * FT * 32 * 2];  // fc B-frags: fc[f][u] tf32
__device__ float g_Ac[MT * KT * 32 * 4];       // adjacency in C-frag layout

__device__ __forceinline__ float tf32r(float x) {
    asm("cvt.rna.tf32.f32 %0, %0;" : "+f"(x)); return x;
}
__device__ __forceinline__ void mma_tf32(float c[4], const uint32_t a[4],
                                         uint32_t b0, uint32_t b1) {
    asm volatile(
        "mma.sync.aligned.m16n8k8.row.col.f32.tf32.tf32.f32 "
        "{%0,%1,%2,%3}, {%4,%5,%6,%7}, {%8,%9}, {%0,%1,%2,%3};"
        : "+f"(c[0]), "+f"(c[1]), "+f"(c[2]), "+f"(c[3])
        : "r"(a[0]), "r"(a[1]), "r"(a[2]), "r"(a[3]), "r"(b0), "r"(b1));
}
// C-fragment (r,2c even/odd pairs) -> A-fragment (r,k) of the same 8-wide tile
__device__ __forceinline__ void c2a(const float c[4], float a[4], int lane) {
    int s0 = (lane & ~3) | ((lane & 3) >> 1);
    int s1 = s0 + 2;
    float v0 = __shfl_sync(~0u, c[0], s0), v1 = __shfl_sync(~0u, c[1], s0);
    float v2 = __shfl_sync(~0u, c[2], s0), v3 = __shfl_sync(~0u, c[3], s0);
    float w0 = __shfl_sync(~0u, c[0], s1), w1 = __shfl_sync(~0u, c[1], s1);
    float w2 = __shfl_sync(~0u, c[2], s1), w3 = __shfl_sync(~0u, c[3], s1);
    bool odd = lane & 1;
    a[0] = odd ? v1 : v0;  a[1] = odd ? v3 : v2;
    a[2] = odd ? w1 : w0;  a[3] = odd ? w3 : w2;
}

// ---------------- operand prep kernels ----------------
__global__ void prep_ga(const float* __restrict__ A, const float* __restrict__ P) {
    int t = blockIdx.x * blockDim.x + threadIdx.x;
    if (t >= Hn * MT * KT * 128) return;
    int i = t & 3, lane = (t >> 2) & 31, rest = t >> 7;
    int kt = rest % KT; rest /= KT;
    int mt = rest % MT; int h = rest / MT;
    int row = (lane >> 2) + (i & 1) * 8;
    int kc  = (lane & 3) + ((i >> 1) << 2);
    int m = 16 * mt + row, n = 8 * kt + kc;
    float v = 0.f;
    if (m < Nn && n < Nn) v = tf32r(A[n * Nn + m] * P[(h * Nn + n) * Nn + m]);
    g_Ga[t] = v;
}
__global__ void prep_kb(const float* __restrict__ KER) {
    int t = blockIdx.x * blockDim.x + threadIdx.x;
    if (t >= Hn * KT * FT * 64) return;
    int i = t & 1, lane = (t >> 1) & 31, rest = t >> 6;
    int kt = rest & 7; rest >>= 3;
    int jt = rest % KT; int h = rest / KT;
    int f = 8 * kt + (lane & 3) + 4 * i;
    int j = 8 * jt + (lane >> 2);
    g_Kb[t] = (j < Nn) ? tf32r(KER[(h * Fn + f) * Nn + j]) : 0.f;
}
__global__ void prep_fb(const float* __restrict__ FC) {
    int t = blockIdx.x * blockDim.x + threadIdx.x;
    if (t >= Hn * FT * FT * 64) return;
    int i = t & 1, lane = (t >> 1) & 31, rest = t >> 6;
    int kt = rest & 7; rest >>= 3;
    int ut = rest & 7; int h = rest >> 3;
    int f = 8 * kt + (lane & 3) + 4 * i;
    int u = 8 * ut + (lane >> 2);
    g_Fb[t] = tf32r(FC[(h * Fn + f) * Un + u]);
}
__global__ void prep_ac(const float* __restrict__ A) {
    int t = blockIdx.x * blockDim.x + threadIdx.x;
    if (t >= MT * KT * 128) return;
    int i = t & 3, lane = (t >> 2) & 31, rest = t >> 7;
    int jt = rest % KT; int mt = rest / KT;
    int r = (lane >> 2) + (i >> 1) * 8;
    int j = 8 * jt + 2 * (lane & 3) + (i & 1);
    int m = 16 * mt + r;
    g_Ac[t] = (m < Nn && j < Nn) ? A[m * Nn + j] : 0.f;
}

// ---------------- main fused kernel ----------------
__global__ __launch_bounds__(THREADS, 1)
void gc_kernel(const float* __restrict__ X, const float* __restrict__ B1,
               const float* __restrict__ B2, float* __restrict__ out)
{
    extern __shared__ float smem[];
    float* XsT = smem;                 // [64][XST] tf32-rounded X^T
    float* b1s = XsT + Fn * XST;       // [200]
    float* b2s = b1s + 200;            // [64]

    const int b = blockIdx.x / Hn;
    const int h = blockIdx.x - b * Hn;
    const int tid = threadIdx.x;
    const int w = tid >> 5;
    const int lane = tid & 31;
    const bool last_h = (h == Hn - 1);

    for (int i = tid; i < 200 * Fn; i += THREADS) {
        int n = i >> 6, f = i & 63;
        float v = (n < Nn) ? X[((size_t)b * Nn + n) * Fn + f] : 0.f;
        XsT[f * XST + n] = tf32r(v);
    }
    for (int i = tid; i < 200; i += THREADS) b1s[i] = (i < Nn) ? B1[h * Nn + i] : 0.f;
    if (tid < Un) b2s[tid] = B2[h * Un + tid];
    __syncthreads();

    if (w >= MT) return;
    const int m0 = 16 * w;
    const int mA = m0 + (lane >> 2);        // row for c0/c1
    const int mB = mA + 8;                  // row for c2/c3

    // ======== FEAT: fC[ft] = G(m-tile) @ X  (k = 200 nodes) ========
    float fC[FT][4];
    #pragma unroll
    for (int t = 0; t < FT; t++) { fC[t][0]=fC[t][1]=fC[t][2]=fC[t][3]=0.f; }
    {
        const float4* gaP = ((const float4*)g_Ga) + ((size_t)(h * MT + w) * KT) * 32 + lane;
        #pragma unroll 1
        for (int kt = 0; kt < KT; kt++) {
            float4 ga = gaP[kt * 32];
            uint32_t a[4] = { __float_as_uint(ga.x), __float_as_uint(ga.y),
                              __float_as_uint(ga.z), __float_as_uint(ga.w) };
            int kc = 8 * kt + (lane & 3);
            #pragma unroll
            for (int ft = 0; ft < FT; ft++) {
                const float* bp = &XsT[(8 * ft + (lane >> 2)) * XST + kc];
                mma_tf32(fC[ft], a, __float_as_uint(bp[0]), __float_as_uint(bp[4]));
            }
        }
    }
    // permute feat C -> A fragments (k = f)
    uint32_t fA[FT][4];
    #pragma unroll
    for (int t = 0; t < FT; t++) {
        float a4[4]; c2a(fC[t], a4, lane);
        #pragma unroll
        for (int q = 0; q < 4; q++) fA[t][q] = __float_as_uint(tf32r(a4[q]));
    }

    // ======== DENSE + masked exp + NODE (fused over j-tiles) ========
    float nC[FT][4];
    #pragma unroll
    for (int t = 0; t < FT; t++) { nC[t][0]=nC[t][1]=nC[t][2]=nC[t][3]=0.f; }
    float s0 = 0.f, s1 = 0.f;

    #pragma unroll 1
    for (int jt = 0; jt < KT; jt++) {
        float dC[4] = {0.f, 0.f, 0.f, 0.f};
        const float2* kbP = ((const float2*)g_Kb) + ((size_t)(h * KT + jt) * FT) * 32 + lane;
        #pragma unroll
        for (int kt = 0; kt < FT; kt++) {
            float2 kb = kbP[kt * 32];
            mma_tf32(dC, fA[kt], __float_as_uint(kb.x), __float_as_uint(kb.y));
        }
        int j = 8 * jt + 2 * (lane & 3);
        float2 b1v = *(const float2*)&b1s[j];
        float4 ac = ((const float4*)g_Ac)[((size_t)(w * KT + jt)) * 32 + lane];
        float e0 = ac.x * __expf(dC[0] + b1v.x);
        float e1 = ac.y * __expf(dC[1] + b1v.y);
        float e2 = ac.z * __expf(dC[2] + b1v.x);
        float e3 = ac.w * __expf(dC[3] + b1v.y);
        s0 += e0 + e1; s1 += e2 + e3;

        if (last_h) {   // raw (unnormalized) mask; rescaled by same thread later
            if (mA < Nn) {
                float* o = out + ((size_t)b * Nn + mA) * OUTC + Hn * Un + j;
                o[0] = e0; if (j < 198) o[1] = e1;
            }
            if (mB < Nn) {
                float* o = out + ((size_t)b * Nn + mB) * OUTC + Hn * Un + j;
                o[0] = e2; if (j < 198) o[1] = e3;
            }
        }
        // node += e-tile @ X (k = this j-tile)
        float ec[4] = {e0, e1, e2, e3}, ea[4];
        c2a(ec, ea, lane);
        uint32_t eA[4];
        #pragma unroll
        for (int q = 0; q < 4; q++) eA[q] = __float_as_uint(tf32r(ea[q]));
        int jc = 8 * jt + (lane & 3);
        #pragma unroll
        for (int ft = 0; ft < FT; ft++) {
            const float* bp = &XsT[(8 * ft + (lane >> 2)) * XST + jc];
            mma_tf32(nC[ft], eA, __float_as_uint(bp[0]), __float_as_uint(bp[4]));
        }
    }
    // row sums across the 4 lanes of each row group
    s0 += __shfl_xor_sync(~0u, s0, 1); s0 += __shfl_xor_sync(~0u, s0, 2);
    s1 += __shfl_xor_sync(~0u, s1, 1); s1 += __shfl_xor_sync(~0u, s1, 2);
    float inv0 = 1.f / s0, inv1 = 1.f / s1;

    if (last_h) {   // normalize mask in-place (same thread wrote these)
        #pragma unroll 1
        for (int jt = 0; jt < KT; jt++) {
            int j = 8 * jt + 2 * (lane & 3);
            if (mA < Nn) {
                float* o = out + ((size_t)b * Nn + mA) * OUTC + Hn * Un + j;
                o[0] *= inv0; if (j < 198) o[1] *= inv0;
            }
            if (mB < Nn) {
                float* o = out + ((size_t)b * Nn + mB) * OUTC + Hn * Un + j;
                o[0] *= inv1; if (j < 198) o[1] *= inv1;
            }
        }
    }
    // normalize node accumulators
    #pragma unroll
    for (int t = 0; t < FT; t++) {
        nC[t][0] *= inv0; nC[t][1] *= inv0;
        nC[t][2] *= inv1; nC[t][3] *= inv1;
    }
    // permute node C -> A fragments (k = f)
    uint32_t nA[FT][4];
    #pragma unroll
    for (int t = 0; t < FT; t++) {
        float a4[4]; c2a(nC[t], a4, lane);
        #pragma unroll
        for (int q = 0; q < 4; q++) nA[t][q] = __float_as_uint(tf32r(a4[q]));
    }

    // ======== FC: out = node @ fc + b2 ========
    #pragma unroll 1
    for (int ut = 0; ut < FT; ut++) {
        float oC[4] = {0.f, 0.f, 0.f, 0.f};
        const float2* fbP = ((const float2*)g_Fb) + ((size_t)(h * FT + ut) * FT) * 32 + lane;
        #pragma unroll
        for (int kt = 0; kt < FT; kt++) {
            float2 fb = fbP[kt * 32];
            mma_tf32(oC, nA[kt], __float_as_uint(fb.x), __float_as_uint(fb.y));
        }
        int u = 8 * ut + 2 * (lane & 3);
        float2 b2v = *(const float2*)&b2s[u];
        if (mA < Nn) {
            float* o = out + ((size_t)b * Nn + mA) * OUTC + h * Un + u;
            o[0] = oC[0] + b2v.x; o[1] = oC[1] + b2v.y;
        }
        if (mB < Nn) {
            float* o = out + ((size_t)b * Nn + mB) * OUTC + h * Un + u;
            o[0] = oC[2] + b2v.x; o[1] = oC[3] + b2v.y;
        }
    }
}

static const size_t SMEM_BYTES = (size_t)(Fn * XST + 200 + Un) * 4;

extern "C" void kernel_launch(void* const* d_in, const int* in_sizes, int n_in,
                              void* d_out, int out_size) {
    const float* X   = (const float*)d_in[0];
    const float* A   = (const float*)d_in[1];
    const float* KER = (const float*)d_in[2];
    const float* P   = (const float*)d_in[3];
    const float* FC  = (const float*)d_in[4];
    const float* B1  = (const float*)d_in[5];
    const float* B2  = (const float*)d_in[6];
    float* out = (float*)d_out;

    prep_ga<<<(Hn * MT * KT * 128 + 255) / 256, 256>>>(A, P);
    prep_kb<<<(Hn * KT * FT * 64 + 255) / 256, 256>>>(KER);
    prep_fb<<<(Hn * FT * FT * 64 + 255) / 256, 256>>>(FC);
    prep_ac<<<(MT * KT * 128 + 255) / 256, 256>>>(A);

    cudaFuncSetAttribute(gc_kernel, cudaFuncAttributeMaxDynamicSharedMemorySize,
                         (int)SMEM_BYTES);
    gc_kernel<<<Bn * Hn, THREADS, SMEM_BYTES>>>(X, B1, B2, out);
}

// round 8
// speedup vs baseline: 2.2220x; 1.5044x over previous
#include <cuda_runtime.h>
#include <math.h>
#include <stdint.h>

#define Bn   512
#define Nn   199
#define Hn   4
#define Fn   64
#define Un   64
#define OUTC 455           // H*U + N
#define MT   13            // m16 tiles covering 200 rows (208)
#define KT   25            // k/j tiles of 8 covering 200
#define FT   8             // f/u tiles of 8 (64)
#define THREADS 512
#define XST  200           // XsT row stride (== 8 mod 32: conflict-free float2)

// Preprocessed operand banks (global, L2-resident)
__device__ float g_Ga[Hn * MT * KT * 32 * 4];  // feat A-frags: G[m][n] tf32
__device__ float g_Kb[Hn * KT * FT * 32 * 2];  // dense B-frags: K[f][j] tf32
__device__ float g_Fb[Hn * FT * FT * 32 * 2];  // fc B-frags: fc[f][u] tf32
__device__ float g_Ac[MT * KT * 32 * 4];       // adjacency in C-frag layout

__device__ __forceinline__ float tf32r(float x) {
    asm("cvt.rna.tf32.f32 %0, %0;" : "+f"(x)); return x;
}
__device__ __forceinline__ void mma_tf32(float c[4], const uint32_t a[4],
                                         uint32_t b0, uint32_t b1) {
    asm volatile(
        "mma.sync.aligned.m16n8k8.row.col.f32.tf32.tf32.f32 "
        "{%0,%1,%2,%3}, {%4,%5,%6,%7}, {%8,%9}, {%0,%1,%2,%3};"
        : "+f"(c[0]), "+f"(c[1]), "+f"(c[2]), "+f"(c[3])
        : "r"(a[0]), "r"(a[1]), "r"(a[2]), "r"(a[3]), "r"(b0), "r"(b1));
}
// C-fragment (r,2c even/odd pairs) -> A-fragment (r,k) of the same 8-wide tile
__device__ __forceinline__ void c2a(const float c[4], float a[4], int lane) {
    int s0 = (lane & ~3) | ((lane & 3) >> 1);
    int s1 = s0 + 2;
    float v0 = __shfl_sync(~0u, c[0], s0), v1 = __shfl_sync(~0u, c[1], s0);
    float v2 = __shfl_sync(~0u, c[2], s0), v3 = __shfl_sync(~0u, c[3], s0);
    float w0 = __shfl_sync(~0u, c[0], s1), w1 = __shfl_sync(~0u, c[1], s1);
    float w2 = __shfl_sync(~0u, c[2], s1), w3 = __shfl_sync(~0u, c[3], s1);
    bool odd = lane & 1;
    a[0] = odd ? v1 : v0;  a[1] = odd ? v3 : v2;
    a[2] = odd ? w1 : w0;  a[3] = odd ? w3 : w2;
}

// ---------------- operand prep kernels ----------------
__global__ void prep_ga(const float* __restrict__ A, const float* __restrict__ P) {
    int t = blockIdx.x * blockDim.x + threadIdx.x;
    if (t >= Hn * MT * KT * 128) return;
    int i = t & 3, lane = (t >> 2) & 31, rest = t >> 7;
    int kt = rest % KT; rest /= KT;
    int mt = rest % MT; int h = rest / MT;
    int row = (lane >> 2) + (i & 1) * 8;
    int kc  = (lane & 3) + ((i >> 1) << 2);
    int m = 16 * mt + row, n = 8 * kt + kc;
    float v = 0.f;
    if (m < Nn && n < Nn) v = tf32r(A[n * Nn + m] * P[(h * Nn + n) * Nn + m]);
    g_Ga[t] = v;
}
__global__ void prep_kb(const float* __restrict__ KER) {
    int t = blockIdx.x * blockDim.x + threadIdx.x;
    if (t >= Hn * KT * FT * 64) return;
    int i = t & 1, lane = (t >> 1) & 31, rest = t >> 6;
    int kt = rest & 7; rest >>= 3;
    int jt = rest % KT; int h = rest / KT;
    int f = 8 * kt + (lane & 3) + 4 * i;
    int j = 8 * jt + (lane >> 2);
    g_Kb[t] = (j < Nn) ? tf32r(KER[(h * Fn + f) * Nn + j]) : 0.f;
}
__global__ void prep_fb(const float* __restrict__ FC) {
    int t = blockIdx.x * blockDim.x + threadIdx.x;
    if (t >= Hn * FT * FT * 64) return;
    int i = t & 1, lane = (t >> 1) & 31, rest = t >> 6;
    int kt = rest & 7; rest >>= 3;
    int ut = rest & 7; int h = rest >> 3;
    int f = 8 * kt + (lane & 3) + 4 * i;
    int u = 8 * ut + (lane >> 2);
    g_Fb[t] = tf32r(FC[(h * Fn + f) * Un + u]);
}
__global__ void prep_ac(const float* __restrict__ A) {
    int t = blockIdx.x * blockDim.x + threadIdx.x;
    if (t >= MT * KT * 128) return;
    int i = t & 3, lane = (t >> 2) & 31, rest = t >> 7;
    int jt = rest % KT; int mt = rest / KT;
    int r = (lane >> 2) + (i >> 1) * 8;
    int j = 8 * jt + 2 * (lane & 3) + (i & 1);
    int m = 16 * mt + r;
    g_Ac[t] = (m < Nn && j < Nn) ? A[m * Nn + j] : 0.f;
}

// ---------------- main fused kernel ----------------
__global__ __launch_bounds__(THREADS, 1)
void gc_kernel(const float* __restrict__ X, const float* __restrict__ B1,
               const float* __restrict__ B2, float* __restrict__ out)
{
    extern __shared__ float smem[];
    float* XsT = smem;                 // [64][XST] tf32 X^T, pair-permuted cols
    float* b1s = XsT + Fn * XST;       // [200]
    float* b2s = b1s + 200;            // [64]

    const int b = blockIdx.x / Hn;
    const int h = blockIdx.x - b * Hn;
    const int tid = threadIdx.x;
    const int w = tid >> 5;
    const int lane = tid & 31;
    const bool last_h = (h == Hn - 1);

    for (int i = tid; i < 200 * Fn; i += THREADS) {
        int n = i >> 6, f = i & 63;
        float v = (n < Nn) ? X[((size_t)b * Nn + n) * Fn + f] : 0.f;
        // pair permutation: slot pair 2c holds (n=c, n=c+4) of each 8-tile
        int col = (n & ~7) | ((n & 3) << 1) | ((n >> 2) & 1);
        XsT[f * XST + col] = tf32r(v);
    }
    for (int i = tid; i < 200; i += THREADS) b1s[i] = (i < Nn) ? B1[h * Nn + i] : 0.f;
    if (tid < Un) b2s[tid] = B2[h * Un + tid];
    __syncthreads();

    if (w >= MT) return;
    const int m0 = 16 * w;
    const int mA = m0 + (lane >> 2);        // row for c0/c1
    const int mB = mA + 8;                  // row for c2/c3
    const int pairOff = 2 * (lane & 3);     // pair slot within tile
    const int bRow = (lane >> 2);           // n-dim row within B tile

    // ======== FEAT: fC[ft] = G(m-tile) @ X  (k = 200 nodes) ========
    float fC[FT][4];
    #pragma unroll
    for (int t = 0; t < FT; t++) { fC[t][0]=fC[t][1]=fC[t][2]=fC[t][3]=0.f; }
    {
        const float4* gaP = ((const float4*)g_Ga) + ((size_t)(h * MT + w) * KT) * 32 + lane;
        float4 ga = __ldg(gaP);
        #pragma unroll 1
        for (int kt = 0; kt < KT; kt++) {
            float4 gan = (kt + 1 < KT) ? __ldg(gaP + (kt + 1) * 32) : ga;
            uint32_t a[4] = { __float_as_uint(ga.x), __float_as_uint(ga.y),
                              __float_as_uint(ga.z), __float_as_uint(ga.w) };
            #pragma unroll
            for (int ft = 0; ft < FT; ft++) {
                float2 xv = *(const float2*)&XsT[(8 * ft + bRow) * XST + 8 * kt + pairOff];
                mma_tf32(fC[ft], a, __float_as_uint(xv.x), __float_as_uint(xv.y));
            }
            ga = gan;
        }
    }
    // permute feat C -> A fragments (k = f)
    uint32_t fA[FT][4];
    #pragma unroll
    for (int t = 0; t < FT; t++) {
        float a4[4]; c2a(fC[t], a4, lane);
        #pragma unroll
        for (int q = 0; q < 4; q++) fA[t][q] = __float_as_uint(tf32r(a4[q]));
    }

    // ======== DENSE + masked exp + NODE (fused over j-tiles) ========
    float nC[FT][4];
    #pragma unroll
    for (int t = 0; t < FT; t++) { nC[t][0]=nC[t][1]=nC[t][2]=nC[t][3]=0.f; }
    float s0 = 0.f, s1 = 0.f;

    const float2* kbP = ((const float2*)g_Kb) + ((size_t)h * KT * FT) * 32 + lane;
    const float4* acP = ((const float4*)g_Ac) + ((size_t)w * KT) * 32 + lane;

    float2 kb[FT]; float4 ac;
    #pragma unroll
    for (int kt = 0; kt < FT; kt++) kb[kt] = __ldg(kbP + kt * 32);
    ac = __ldg(acP);

    #pragma unroll 1
    for (int jt = 0; jt < KT; jt++) {
        float2 kbn[FT]; float4 acn;
        if (jt + 1 < KT) {
            #pragma unroll
            for (int kt = 0; kt < FT; kt++)
                kbn[kt] = __ldg(kbP + ((jt + 1) * FT + kt) * 32);
            acn = __ldg(acP + (jt + 1) * 32);
        } else {
            #pragma unroll
            for (int kt = 0; kt < FT; kt++) kbn[kt] = kb[kt];
            acn = ac;
        }

        float dC[4] = {0.f, 0.f, 0.f, 0.f};
        #pragma unroll
        for (int kt = 0; kt < FT; kt++)
            mma_tf32(dC, fA[kt], __float_as_uint(kb[kt].x), __float_as_uint(kb[kt].y));

        int j = 8 * jt + 2 * (lane & 3);
        float2 b1v = *(const float2*)&b1s[j];
        float e0 = ac.x * __expf(dC[0] + b1v.x);
        float e1 = ac.y * __expf(dC[1] + b1v.y);
        float e2 = ac.z * __expf(dC[2] + b1v.x);
        float e3 = ac.w * __expf(dC[3] + b1v.y);
        s0 += e0 + e1; s1 += e2 + e3;

        if (last_h) {   // raw (unnormalized) mask; rescaled by same thread later
            if (mA < Nn) {
                float* o = out + ((size_t)b * Nn + mA) * OUTC + Hn * Un + j;
                o[0] = e0; if (j < 198) o[1] = e1;
            }
            if (mB < Nn) {
                float* o = out + ((size_t)b * Nn + mB) * OUTC + Hn * Un + j;
                o[0] = e2; if (j < 198) o[1] = e3;
            }
        }
        // node += e-tile @ X (k = this j-tile)
        float ec[4] = {e0, e1, e2, e3}, ea[4];
        c2a(ec, ea, lane);
        uint32_t eA[4];
        #pragma unroll
        for (int q = 0; q < 4; q++) eA[q] = __float_as_uint(tf32r(ea[q]));
        #pragma unroll
        for (int ft = 0; ft < FT; ft++) {
            float2 xv = *(const float2*)&XsT[(8 * ft + bRow) * XST + 8 * jt + pairOff];
            mma_tf32(nC[ft], eA, __float_as_uint(xv.x), __float_as_uint(xv.y));
        }
        #pragma unroll
        for (int kt = 0; kt < FT; kt++) kb[kt] = kbn[kt];
        ac = acn;
    }
    // row sums across the 4 lanes of each row group
    s0 += __shfl_xor_sync(~0u, s0, 1); s0 += __shfl_xor_sync(~0u, s0, 2);
    s1 += __shfl_xor_sync(~0u, s1, 1); s1 += __shfl_xor_sync(~0u, s1, 2);
    float inv0 = 1.f / s0, inv1 = 1.f / s1;

    if (last_h) {   // normalize mask in-place (same thread wrote these)
        #pragma unroll 1
        for (int jt = 0; jt < KT; jt++) {
            int j = 8 * jt + 2 * (lane & 3);
            if (mA < Nn) {
                float* o = out + ((size_t)b * Nn + mA) * OUTC + Hn * Un + j;
                o[0] *= inv0; if (j < 198) o[1] *= inv0;
            }
            if (mB < Nn) {
                float* o = out + ((size_t)b * Nn + mB) * OUTC + Hn * Un + j;
                o[0] *= inv1; if (j < 198) o[1] *= inv1;
            }
        }
    }
    // normalize node accumulators
    #pragma unroll
    for (int t = 0; t < FT; t++) {
        nC[t][0] *= inv0; nC[t][1] *= inv0;
        nC[t][2] *= inv1; nC[t][3] *= inv1;
    }
    // permute node C -> A fragments (k = f)
    uint32_t nA[FT][4];
    #pragma unroll
    for (int t = 0; t < FT; t++) {
        float a4[4]; c2a(nC[t], a4, lane);
        #pragma unroll
        for (int q = 0; q < 4; q++) nA[t][q] = __float_as_uint(tf32r(a4[q]));
    }

    // ======== FC: out = node @ fc + b2 ========
    const float2* fbP = ((const float2*)g_Fb) + ((size_t)h * FT * FT) * 32 + lane;
    #pragma unroll 1
    for (int ut = 0; ut < FT; ut++) {
        float oC[4] = {0.f, 0.f, 0.f, 0.f};
        #pragma unroll
        for (int kt = 0; kt < FT; kt++) {
            float2 fb = __ldg(fbP + (ut * FT + kt) * 32);
            mma_tf32(oC, nA[kt], __float_as_uint(fb.x), __float_as_uint(fb.y));
        }
        int u = 8 * ut + 2 * (lane & 3);
        float2 b2v = *(const float2*)&b2s[u];
        if (mA < Nn) {
            float* o = out + ((size_t)b * Nn + mA) * OUTC + h * Un + u;
            o[0] = oC[0] + b2v.x; o[1] = oC[1] + b2v.y;
        }
        if (mB < Nn) {
            float* o = out + ((size_t)b * Nn + mB) * OUTC + h * Un + u;
            o[0] = oC[2] + b2v.x; o[1] = oC[3] + b2v.y;
        }
    }
}

static const size_t SMEM_BYTES = (size_t)(Fn * XST + 200 + Un) * 4;

extern "C" void kernel_launch(void* const* d_in, const int* in_sizes, int n_in,
                              void* d_out, int out_size) {
    const float* X   = (const float*)d_in[0];
    const float* A   = (const float*)d_in[1];
    const float* KER = (const float*)d_in[2];
    const float* P   = (const float*)d_in[3];
    const float* FC  = (const float*)d_in[4];
    const float* B1  = (const float*)d_in[5];
    const float* B2  = (const float*)d_in[6];
    float* out = (float*)d_out;

    prep_ga<<<(Hn * MT * KT * 128 + 255) / 256, 256>>>(A, P);
    prep_kb<<<(Hn * KT * FT * 64 + 255) / 256, 256>>>(KER);
    prep_fb<<<(Hn * FT * FT * 64 + 255) / 256, 256>>>(FC);
    prep_ac<<<(MT * KT * 128 + 255) / 256, 256>>>(A);

    cudaFuncSetAttribute(gc_kernel, cudaFuncAttributeMaxDynamicSharedMemorySize,
                         (int)SMEM_BYTES);
    gc_kernel<<<Bn * Hn, THREADS, SMEM_BYTES>>>(X, B1, B2, out);
}